// round 12
// baseline (speedup 1.0000x reference)
#include <cuda_runtime.h>
#include <math.h>
#include <stdint.h>

namespace {
constexpr int H  = 256;
constexpr int I  = 128;
constexpr int R  = 32;
constexpr int B  = 16;
constexpr int T  = 48;
constexpr int H3 = 768;

constexpr long V_OFF    = 0;
constexpr long H_OFF    = V_OFF  + (long)B * H;
constexpr long DU_OFF   = H_OFF  + (long)B * H;
constexpr long TE_OFF   = DU_OFF + (long)B * H * H;
constexpr long TEE_OFF  = TE_OFF + (long)B * H;
constexpr long OUTS_OFF = TEE_OFF + (long)B * H * H;
constexpr long MODS_OFF = OUTS_OFF + (long)T * B * H;

// per consumer CTA: 8 peers * 32 warps * (3*4B + 8B) = 5120
constexpr unsigned EXPECT_BYTES = 5120;
}

typedef unsigned long long ull;

__device__ float g_Wx[(size_t)T * B * H3];   // LN(x @ Wx2h^T + b), prologue

struct SM {
  float Ws[96 * 256];      // W_h2h slice, rows: [0:32)=z, [32:64)=r, [64:96)=dv
  float Wm[32 * 256];      // W_h2mod
  float  whx[2][H3];       // exchanged pre-LN vector (bias+plastic included)
  float2 stats[2][256];    // exchanged per-warp (sum, sumsq)
  float4 bndU[2][1024];    // clip upper bounds, SoA [chunk][tid]
  float4 bndL[2][1024];
  float h[H];
  float te[H];
  float mod[R];
  float2 modred[32];
  float2 red[32];
  ull mbar[2];
};

__device__ __forceinline__ float sigm(float x) { return 1.0f / (1.0f + __expf(-x)); }

__device__ __forceinline__ void cluster_sync_() {
  asm volatile("barrier.cluster.arrive.aligned;\n\tbarrier.cluster.wait.aligned;" ::: "memory");
}

__device__ __forceinline__ uint32_t smem_u32(const void* p) {
  return (uint32_t)__cvta_generic_to_shared(p);
}

__device__ __forceinline__ uint32_t mapa_u32(uint32_t addr, uint32_t peer) {
  uint32_t r;
  asm("mapa.shared::cluster.u32 %0, %1, %2;" : "=r"(r) : "r"(addr), "r"(peer));
  return r;
}

__device__ __forceinline__ void st_async_1f(uint32_t raddr, float a, uint32_t rmbar) {
  asm volatile("st.async.shared::cluster.mbarrier::complete_tx::bytes.b32 [%0], %1, [%2];"
               :: "r"(raddr), "r"(__float_as_uint(a)), "r"(rmbar) : "memory");
}

__device__ __forceinline__ void st_async_2f(uint32_t raddr, float a, float b, uint32_t rmbar) {
  ull pk = (ull)__float_as_uint(a) | ((ull)__float_as_uint(b) << 32);
  asm volatile("st.async.shared::cluster.mbarrier::complete_tx::bytes.b64 [%0], %1, [%2];"
               :: "r"(raddr), "l"(pk), "r"(rmbar) : "memory");
}

__device__ __forceinline__ void mbar_arm(uint32_t mbar, uint32_t bytes) {
  asm volatile("mbarrier.arrive.expect_tx.shared.b64 _, [%0], %1;"
               :: "r"(mbar), "r"(bytes) : "memory");
}

__device__ __forceinline__ void mbar_init(uint32_t mbar, uint32_t count) {
  asm volatile("mbarrier.init.shared.b64 [%0], %1;" :: "r"(mbar), "r"(count) : "memory");
}

__device__ __forceinline__ void mbar_wait(uint32_t mbar, uint32_t parity) {
  uint32_t done;
  asm volatile("{\n\t.reg .pred p;\n\t"
               "mbarrier.try_wait.parity.acquire.cta.shared::cta.b64 p, [%1], %2;\n\t"
               "selp.b32 %0, 1, 0, p;\n\t}"
               : "=r"(done) : "r"(mbar), "r"(parity) : "memory");
  while (!done) {
    asm volatile("{\n\t.reg .pred p;\n\t"
                 "mbarrier.try_wait.parity.acquire.cta.shared::cta.b64 p, [%1], %2, 0x989680;\n\t"
                 "selp.b32 %0, 1, 0, p;\n\t}"
                 : "=r"(done) : "r"(mbar), "r"(parity) : "memory");
  }
}

// ---------- Blackwell f32x2 packed helpers ----------
__device__ __forceinline__ ull pack2(float lo, float hi) {
  ull r; asm("mov.b64 %0, {%1, %2};" : "=l"(r) : "f"(lo), "f"(hi)); return r;
}
__device__ __forceinline__ void unpack2(ull v, float& lo, float& hi) {
  asm("mov.b64 {%0, %1}, %2;" : "=f"(lo), "=f"(hi) : "l"(v));
}
__device__ __forceinline__ ull mul2(ull a, ull b) {
  ull d; asm("mul.rn.f32x2 %0, %1, %2;" : "=l"(d) : "l"(a), "l"(b)); return d;
}
__device__ __forceinline__ ull fma2(ull a, ull b, ull c) {
  ull d; asm("fma.rn.f32x2 %0, %1, %2, %3;" : "=l"(d) : "l"(a), "l"(b), "l"(c)); return d;
}

// packed dot: weight row in smem (2x LDS.128) with h2[4]
__device__ __forceinline__ float dotrow(const ulonglong2* Wrow, int lane, const ull* h2) {
  ulonglong2 wa = Wrow[lane];
  ulonglong2 wb = Wrow[32 + lane];
  ull acc = mul2(wa.x, h2[0]);
  acc = fma2(wa.y, h2[1], acc);
  acc = fma2(wb.x, h2[2], acc);
  acc = fma2(wb.y, h2[3], acc);
  float lo, hi; unpack2(acc, lo, hi);
  return lo + hi;
}

__global__ void __cluster_dims__(8, 1, 1) __launch_bounds__(1024, 1)
sgru_persistent(const float* __restrict__ x_in,
                const float* __restrict__ h0,
                const float* __restrict__ v0,
                const float* __restrict__ dU0,
                const float* __restrict__ te0,
                const float* __restrict__ tE0,
                const float* __restrict__ Wx2h,
                const float* __restrict__ bx2h,
                const float* __restrict__ Wh2h,
                const float* __restrict__ bh2h,
                const float* __restrict__ lnxg,
                const float* __restrict__ lnxb,
                const float* __restrict__ lnhg,
                const float* __restrict__ lnhb,
                const float* __restrict__ Wh2mod,
                const float* __restrict__ bh2mod,
                const float* __restrict__ Wmod2h,
                const float* __restrict__ bmod2h,
                const float* __restrict__ alpha,
                const float* __restrict__ tauU,
                float* __restrict__ out)
{
  extern __shared__ unsigned char smem_raw[];
  SM* S = reinterpret_cast<SM*>(smem_raw);
  const int tid  = threadIdx.x;
  const int wid  = tid >> 5;          // 0..31
  const int lane = tid & 31;
  const int rank = blockIdx.x & 7;
  const int b    = blockIdx.x >> 3;
  const int gi   = 32 * rank + wid;   // this warp's row
  const bool lower = (tid < 256);
  const bool mid   = (tid >= 256 && tid < 512);
  const int  elem  = tid & 255;

  const float a0      = alpha[0];
  const float sp_a    = (a0 > 0.f) ? (a0 + log1pf(expf(-a0))) : log1pf(expf(a0));
  const float inv_spa = 1.0f / sp_a;
  const float tau     = sigm(tauU[0]);
  const float bm0     = bmod2h[0];
  const float bm1     = bmod2h[1];
  const ull   omt2    = pack2(1.f - tau, 1.f - tau);

  // ================= prologue: Wx = x @ Wx2h^T + b (raw) =====================
  {
    const float4* WxA = (const float4*)(Wx2h + (size_t)96 * rank * I);
    float4* Ws4w = (float4*)S->Ws;
    for (int i = tid; i < 96 * I / 4; i += 1024) Ws4w[i] = WxA[i];
  }
  __syncthreads();
  {
    const float4* Ws4c = (const float4*)S->Ws;
    for (int it = 0; it < 2; ++it) {
      int t = wid + 32 * it;
      if (t < T) {
        float4 x4 = ((const float4*)x_in)[(size_t)(t * B + b) * 32 + lane];
        for (int g = 0; g < 6; ++g) {
          float acc[16];
#pragma unroll
          for (int k = 0; k < 16; ++k) {
            float4 w = Ws4c[(g * 16 + k) * 32 + lane];
            acc[k] = w.x * x4.x + w.y * x4.y + w.z * x4.z + w.w * x4.w;
          }
#pragma unroll
          for (int k = 0; k < 8; ++k) {
            float a = (lane & 16) ? acc[k + 8] : acc[k];
            float c = (lane & 16) ? acc[k] : acc[k + 8];
            acc[k] = a + __shfl_xor_sync(~0u, c, 16);
          }
#pragma unroll
          for (int k = 0; k < 4; ++k) {
            float a = (lane & 8) ? acc[k + 4] : acc[k];
            float c = (lane & 8) ? acc[k] : acc[k + 4];
            acc[k] = a + __shfl_xor_sync(~0u, c, 8);
          }
#pragma unroll
          for (int k = 0; k < 2; ++k) {
            float a = (lane & 4) ? acc[k + 2] : acc[k];
            float c = (lane & 4) ? acc[k] : acc[k + 2];
            acc[k] = a + __shfl_xor_sync(~0u, c, 4);
          }
#pragma unroll
          for (int o = 2; o; o >>= 1) {
            acc[0] += __shfl_xor_sync(~0u, acc[0], o);
            acc[1] += __shfl_xor_sync(~0u, acc[1], o);
          }
          if ((lane & 3) == 0) {
            int p = (lane >> 2) & 7;
            int o = 96 * rank + g * 16 + 2 * p;
            float2 bias = *(const float2*)&bx2h[o];
            float2 val = make_float2(acc[0] + bias.x, acc[1] + bias.y);
            *(float2*)&g_Wx[(size_t)(t * B + b) * H3 + o] = val;
          }
        }
      }
    }
  }
  cluster_sync_();

  // ================= prologue LN over g_Wx (768 elems over 1024 thr) =========
  for (int t = rank; t < T; t += 8) {
    float* base = &g_Wx[(size_t)(t * B + b) * H3];
    float e0 = (tid < H3) ? base[tid] : 0.f;
    float s1 = e0, s2 = e0 * e0;
#pragma unroll
    for (int o = 16; o; o >>= 1) {
      s1 += __shfl_xor_sync(~0u, s1, o);
      s2 += __shfl_xor_sync(~0u, s2, o);
    }
    if (lane == 0) S->red[wid] = make_float2(s1, s2);
    __syncthreads();
    float ssum = 0.f, ssq = 0.f;
#pragma unroll
    for (int i = 0; i < 32; ++i) { float2 rr = S->red[i]; ssum += rr.x; ssq += rr.y; }
    float mu   = ssum * (1.0f / H3);
    float var  = ssq * (1.0f / H3) - mu * mu;
    float rstd = rsqrtf(var + 1e-5f);
    if (tid < H3) base[tid] = (e0 - mu) * rstd * lnxg[tid] + lnxb[tid];
    __syncthreads();
  }

  // ================= load main-loop smem + register state ===================
  {
    float4* Ws4w = (float4*)S->Ws;
    for (int i = tid; i < 96 * 64; i += 1024) {
      int q = i >> 6, c4 = i & 63;
      int grow = ((q >> 5) << 8) + 32 * rank + (q & 31);
      Ws4w[i] = ((const float4*)(Wh2h + (size_t)grow * H))[c4];
    }
    const float4* Wm4s = (const float4*)Wh2mod;
    float4* Wm4w = (float4*)S->Wm;
    for (int i = tid; i < 32 * 64; i += 1024) Wm4w[i] = Wm4s[i];
  }
  // phase-2 split state
  float v_own = 0.f, te_rep = 0.f, h_rep = 0.f;
  float gA = 0.f, lbA = 0.f, gC = 0.f, lbC = 0.f;
  if (tid < 512) { gA = lnhg[tid]; lbA = lnhb[tid]; }
  if (lower) {
    v_own = v0[b * H + elem];
    S->h[elem] = h0[b * H + elem];
    gC = lnhg[512 + elem]; lbC = lnhb[512 + elem];
  } else if (mid) {
    h_rep  = h0[b * H + elem];
    te_rep = te0[b * H + elem];
    S->te[elem] = te_rep;
  }

  const uint32_t mb_local = smem_u32(&S->mbar[0]);
  if (tid == 0) {
    mbar_init(mb_local, 1);
    mbar_init(mb_local + 8, 1);
    mbar_arm(mb_local, EXPECT_BYTES);
    mbar_arm(mb_local + 8, EXPECT_BYTES);
  }

  // per-lane group (0=z,1=r,2=dv,3=stats) and bias
  const int grp = lane >> 3;
  const float bias_l = (grp < 3) ? bh2h[256 * grp + gi] : 0.f;
  const float wsA = Wmod2h[wid];
  const float wmA = Wmod2h[R + wid];
  const float bhm_l = bh2mod[wid];

  // dU / tE row gi as PACKED f32x2 state; clip bounds -> smem SoA
  ull dU2[4], tE2[4];
  {
    const ulonglong2* du8 = (const ulonglong2*)(dU0 + ((size_t)b * H + gi) * H);
    const ulonglong2* tE8 = (const ulonglong2*)(tE0 + ((size_t)b * H + gi) * H);
    const float4* wv4 = (const float4*)(Wh2h + (size_t)(512 + gi) * H);
    ulonglong2 A = du8[lane], C = du8[32 + lane];
    dU2[0] = A.x; dU2[1] = A.y; dU2[2] = C.x; dU2[3] = C.y;
    A = tE8[lane]; C = tE8[32 + lane];
    tE2[0] = A.x; tE2[1] = A.y; tE2[2] = C.x; tE2[3] = C.y;
    float4 a = wv4[lane], c = wv4[32 + lane];
    float wv[8] = {a.x,a.y,a.z,a.w,c.x,c.y,c.z,c.w};
    float4 u0, u1, l0, l1;
    u0.x =  fmaxf(1.f - wv[0], 0.f) * inv_spa;
    u0.y =  fmaxf(1.f - wv[1], 0.f) * inv_spa;
    u0.z =  fmaxf(1.f - wv[2], 0.f) * inv_spa;
    u0.w =  fmaxf(1.f - wv[3], 0.f) * inv_spa;
    u1.x =  fmaxf(1.f - wv[4], 0.f) * inv_spa;
    u1.y =  fmaxf(1.f - wv[5], 0.f) * inv_spa;
    u1.z =  fmaxf(1.f - wv[6], 0.f) * inv_spa;
    u1.w =  fmaxf(1.f - wv[7], 0.f) * inv_spa;
    l0.x = -fmaxf(1.f + wv[0], 0.f) * inv_spa;
    l0.y = -fmaxf(1.f + wv[1], 0.f) * inv_spa;
    l0.z = -fmaxf(1.f + wv[2], 0.f) * inv_spa;
    l0.w = -fmaxf(1.f + wv[3], 0.f) * inv_spa;
    l1.x = -fmaxf(1.f + wv[4], 0.f) * inv_spa;
    l1.y = -fmaxf(1.f + wv[5], 0.f) * inv_spa;
    l1.z = -fmaxf(1.f + wv[6], 0.f) * inv_spa;
    l1.w = -fmaxf(1.f + wv[7], 0.f) * inv_spa;
    S->bndU[0][tid] = u0; S->bndU[1][tid] = u1;
    S->bndL[0][tid] = l0; S->bndL[1][tid] = l1;
  }

  const uint32_t whx_peer   = mapa_u32(smem_u32(&S->whx[0][0]),   lane & 7);
  const uint32_t stats_peer = mapa_u32(smem_u32(&S->stats[0][0]), lane & 7);
  const uint32_t mbar_peer  = mapa_u32(mb_local,                  lane & 7);

  cluster_sync_();   // orders mbarrier init + smem state cluster-wide

  // packed h column registers
  ull h2[4];
  {
    const ulonglong2* h8 = (const ulonglong2*)S->h;
    ulonglong2 a = h8[lane], c = h8[32 + lane];
    h2[0] = a.x; h2[1] = a.y; h2[2] = c.x; h2[3] = c.y;
  }

  // initial plastic partial (packed)
  float pp;
  {
    ull p0 = mul2(dU2[0], h2[0]);
    p0 = fma2(dU2[1], h2[1], p0);
    p0 = fma2(dU2[2], h2[2], p0);
    p0 = fma2(dU2[3], h2[3], p0);
    float lo, hi; unpack2(p0, lo, hi); pp = lo + hi;
  }

  const ulonglong2* Ws8 = (const ulonglong2*)S->Ws;
  const ulonglong2* Wm8 = (const ulonglong2*)S->Wm;

  // preloop: 3 GEMV dots for t=0 (plastic added at loop top)
  float acc[4];
  acc[0] = dotrow(Ws8 + (wid)      * 64, lane, h2);   // z
  acc[1] = dotrow(Ws8 + (32 + wid) * 64, lane, h2);   // r
  acc[2] = dotrow(Ws8 + (64 + wid) * 64, lane, h2);   // dv

  // wx pipeline registers for t=0
  float wxA = 0.f, wxC = 0.f;
  {
    const float* wxp = &g_Wx[(size_t)(0 * B + b) * H3];
    if (tid < 512) wxA = __ldcg(wxp + tid);
    if (lower)     wxC = __ldcg(wxp + 512 + elem);
  }

  // ================= main scan ==============================================
  int par = 0;
  for (int t = 0; t < T; ++t, par ^= 1) {
    const uint32_t use_parity = (uint32_t)(t >> 1) & 1u;

    // ---- add plastic, fold 4 -> 1, stats, exchange ----
    acc[2] += sp_a * pp;
    acc[3] = 0.f;
#pragma unroll
    for (int k = 0; k < 2; ++k) {
      float a = (lane & 16) ? acc[k + 2] : acc[k];
      float c = (lane & 16) ? acc[k] : acc[k + 2];
      acc[k] = a + __shfl_xor_sync(~0u, c, 16);
    }
    {
      float a = (lane & 8) ? acc[1] : acc[0];
      float c = (lane & 8) ? acc[0] : acc[1];
      acc[0] = a + __shfl_xor_sync(~0u, c, 8);
    }
#pragma unroll
    for (int o = 4; o; o >>= 1)
      acc[0] += __shfl_xor_sync(~0u, acc[0], o);
    float val = acc[0] + bias_l;                 // grp3 lanes: 0 + 0
    float v8  = __shfl_xor_sync(~0u, val, 8);
    float v16 = __shfl_xor_sync(~0u, val, 16);
    float v24 = __shfl_xor_sync(~0u, val, 24);
    float u = val + v8 + v16 + v24;
    float q = val * val + v8 * v8 + v16 * v16 + v24 * v24;

    {
      const uint32_t rmbar = mbar_peer + 8u * (uint32_t)par;
      if (grp < 3) {
        st_async_1f(whx_peer + (uint32_t)(par * H3 + 256 * grp + gi) * 4u, val, rmbar);
      } else {
        st_async_2f(stats_peer + (uint32_t)(par * 256 + rank * 32 + wid) * 8u, u, q, rmbar);
      }
    }

    if (wid < 16) {
      mbar_wait(mb_local + 8u * (uint32_t)par, use_parity);
      if (tid == 0) mbar_arm(mb_local + 8u * (uint32_t)par, EXPECT_BYTES);
    }

    // ---- stats combine + split phase 2 (threads < 512) ----
    if (tid < 512) {
      const float4* st4 = (const float4*)&S->stats[par][0];
      float4 A = st4[lane], Bv = st4[32 + lane];
      float4 C = st4[64 + lane], D = st4[96 + lane];
      float su = A.x + A.z + Bv.x + Bv.z + C.x + C.z + D.x + D.z;
      float sq = A.y + A.w + Bv.y + Bv.w + C.y + C.w + D.y + D.w;
#pragma unroll
      for (int o = 16; o; o >>= 1) {
        su += __shfl_xor_sync(~0u, su, o);
        sq += __shfl_xor_sync(~0u, sq, o);
      }
      float mu   = su * (1.0f / H3);
      float var  = sq * (1.0f / H3) - mu * mu;
      float rstd = rsqrtf(var + 1e-5f);

      if (lower) {
        float w0 = S->whx[par][elem];
        float w2 = S->whx[par][512 + elem];
        float pre0 = (w0 - mu) * rstd * gA + lbA + wxA;
        float pre2 = (w2 - mu) * rstd * gC + lbC + wxC;
        float z  = sigm(pre0);
        float vn = v_own + z * (pre2 - v_own);
        float hn = fmaxf(vn, 0.f);
        v_own = vn;
        S->h[elem] = hn;
        if (rank == 0) out[OUTS_OFF + (size_t)(t * B + b) * H + elem] = hn;
      } else {
        float w1 = S->whx[par][256 + elem];
        float pre1 = (w1 - mu) * rstd * gA + lbA + wxA;
        float r  = sigm(pre1);
        float tn = te_rep + r * (h_rep - te_rep);   // OLD h replica
        te_rep = tn;
        S->te[elem] = tn;
      }
    }
    __syncthreads();                               // (B)

    // ---- prefetch wx for t+1 ----
    if (t < T - 1) {
      const float* wxn = &g_Wx[(size_t)((t + 1) * B + b) * H3];
      if (tid < 512) wxA = __ldcg(wxn + tid);
      if (lower)     wxC = __ldcg(wxn + 512 + elem);
    }

    // ---- reload packed h columns; mid updates h replica ----
    {
      const ulonglong2* h8 = (const ulonglong2*)S->h;
      ulonglong2 a = h8[lane], c = h8[32 + lane];
      h2[0] = a.x; h2[1] = a.y; h2[2] = c.x; h2[3] = c.y;
      if (mid) h_rep = S->h[elem];
    }

    // ---- GEMV dots for NEXT step ----
    acc[0] = dotrow(Ws8 + (wid)      * 64, lane, h2);
    acc[1] = dotrow(Ws8 + (32 + wid) * 64, lane, h2);
    acc[2] = dotrow(Ws8 + (64 + wid) * 64, lane, h2);

    // ---- mod = relu(h_new @ Wm^T + b), 1 row/warp ----
    {
      float m = dotrow(Wm8 + wid * 64, lane, h2);
#pragma unroll
      for (int o = 16; o; o >>= 1) m += __shfl_xor_sync(~0u, m, o);
      float mval = fmaxf(m + bhm_l, 0.f);
      if (lane == 0) {
        S->modred[wid] = make_float2(wsA * mval, wmA * mval);
        S->mod[wid] = mval;
      }
    }
    __syncthreads();                               // (C)

    // ---- s, m from modred (32 entries) ----
    float2 mr = S->modred[lane];
    float t0 = mr.x, t1 = mr.y;
#pragma unroll
    for (int o = 16; o; o >>= 1) {
      t0 += __shfl_xor_sync(~0u, t0, o);
      t1 += __shfl_xor_sync(~0u, t1, o);
    }
    float s = sigm(t0 + bm0);
    float m = t1 + bm1;
    if (rank == 0 && tid < R)
      out[MODS_OFF + (size_t)(t * B + b) * R + tid] = S->mod[tid];

    // ---- G: packed dU / tE update + clip + plastic partial ----
    {
      const ull s2   = pack2(s, s);
      const ull oms2 = pack2(1.f - s, 1.f - s);
      const float tm = tau * m;
      const ull tm2  = pack2(tm, tm);
      float hni  = S->h[gi];
      float teni = S->te[gi];
      const ull hni2 = pack2(hni, hni);
      const ull nte2 = pack2(-teni, -teni);
      ull te2p[4];
      {
        const ulonglong2* t8 = (const ulonglong2*)S->te;
        ulonglong2 a = t8[lane], c = t8[32 + lane];
        te2p[0] = a.x; te2p[1] = a.y; te2p[2] = c.x; te2p[3] = c.y;
      }
      float4 u0 = S->bndU[0][tid], u1 = S->bndU[1][tid];
      float4 l0 = S->bndL[0][tid], l1 = S->bndL[1][tid];
      float up[8] = {u0.x,u0.y,u0.z,u0.w,u1.x,u1.y,u1.z,u1.w};
      float lo[8] = {l0.x,l0.y,l0.z,l0.w,l1.x,l1.y,l1.z,l1.w};
      ull pp2 = 0;
      bool first = true;
#pragma unroll
      for (int p = 0; p < 4; ++p) {
        ull outer = fma2(nte2, h2[p], mul2(hni2, te2p[p]));
        ull E = fma2(s2, outer, mul2(oms2, tE2[p]));
        tE2[p] = E;
        ull dt = fma2(tm2, E, mul2(omt2, dU2[p]));
        float d0, d1; unpack2(dt, d0, d1);
        d0 = fminf(fmaxf(d0, lo[2*p]),     up[2*p]);
        d1 = fminf(fmaxf(d1, lo[2*p + 1]), up[2*p + 1]);
        ull dp = pack2(d0, d1);
        dU2[p] = dp;
        if (first) { pp2 = mul2(dp, h2[p]); first = false; }
        else       { pp2 = fma2(dp, h2[p], pp2); }
      }
      float plo, phi; unpack2(pp2, plo, phi);
      pp = plo + phi;
    }
  }

  // ================= epilogue ===============================================
  if (rank == 0) {
    if (lower) {
      out[V_OFF + b * H + elem] = v_own;
      out[H_OFF + b * H + elem] = S->h[elem];
    } else if (mid) {
      out[TE_OFF + b * H + elem] = te_rep;
    }
  }
  {
    size_t rb = ((size_t)b * H + gi) * H;
    ulonglong2 a, c;
    a.x = dU2[0]; a.y = dU2[1];
    c.x = dU2[2]; c.y = dU2[3];
    ((ulonglong2*)(out + DU_OFF + rb))[lane]      = a;
    ((ulonglong2*)(out + DU_OFF + rb))[32 + lane] = c;
    a.x = tE2[0]; a.y = tE2[1];
    c.x = tE2[2]; c.y = tE2[3];
    ((ulonglong2*)(out + TEE_OFF + rb))[lane]      = a;
    ((ulonglong2*)(out + TEE_OFF + rb))[32 + lane] = c;
  }
}

extern "C" void kernel_launch(void* const* d_in, const int* in_sizes, int n_in,
                              void* d_out, int out_size) {
  (void)in_sizes; (void)n_in; (void)out_size;
  const float* x_in   = (const float*)d_in[0];
  const float* h0     = (const float*)d_in[1];
  const float* v0     = (const float*)d_in[2];
  const float* dU0    = (const float*)d_in[3];
  const float* te0    = (const float*)d_in[4];
  const float* tE0    = (const float*)d_in[5];
  const float* Wx2h   = (const float*)d_in[6];
  const float* bx2h   = (const float*)d_in[7];
  const float* Wh2h   = (const float*)d_in[8];
  const float* bh2h   = (const float*)d_in[9];
  const float* lnxg   = (const float*)d_in[10];
  const float* lnxb   = (const float*)d_in[11];
  const float* lnhg   = (const float*)d_in[12];
  const float* lnhb   = (const float*)d_in[13];
  const float* Wh2mod = (const float*)d_in[14];
  const float* bh2mod = (const float*)d_in[15];
  const float* Wmod2h = (const float*)d_in[16];
  const float* bmod2h = (const float*)d_in[17];
  const float* alpha  = (const float*)d_in[18];
  const float* tauU   = (const float*)d_in[19];
  float* out = (float*)d_out;

  cudaFuncSetAttribute(sgru_persistent,
                       cudaFuncAttributeMaxDynamicSharedMemorySize,
                       (int)sizeof(SM));
  sgru_persistent<<<B * 8, 1024, sizeof(SM)>>>(
      x_in, h0, v0, dU0, te0, tE0, Wx2h, bx2h, Wh2h, bh2h,
      lnxg, lnxb, lnhg, lnhb, Wh2mod, bh2mod, Wmod2h, bmod2h,
      alpha, tauU, out);
}

// round 13
// speedup vs baseline: 1.3330x; 1.3330x over previous
#include <cuda_runtime.h>
#include <math.h>
#include <stdint.h>

namespace {
constexpr int H  = 256;
constexpr int I  = 128;
constexpr int R  = 32;
constexpr int B  = 16;
constexpr int T  = 48;
constexpr int H3 = 768;

constexpr long V_OFF    = 0;
constexpr long H_OFF    = V_OFF  + (long)B * H;
constexpr long DU_OFF   = H_OFF  + (long)B * H;
constexpr long TE_OFF   = DU_OFF + (long)B * H * H;
constexpr long TEE_OFF  = TE_OFF + (long)B * H;
constexpr long OUTS_OFF = TEE_OFF + (long)B * H * H;
constexpr long MODS_OFF = OUTS_OFF + (long)T * B * H;

constexpr unsigned EXPECT_BYTES = 4096;  // 8 peers * 16 warps * 4 stores * 8B
}

typedef unsigned long long ull;

__device__ float g_Wx[(size_t)T * B * H3];   // LN(x @ Wx2h^T + b), prologue

struct SM {
  float Ws[96 * 256];      // W_h2h slice, reordered: [0:32)=z, [32:64)=r, [64:96)=dv rows
  float Wm[32 * 256];      // W_h2mod
  float  whx[2][H3];       // st.async-exchanged pre-LN vector (bias+plastic included)
  float2 stats[2][128];    // st.async-exchanged per-warp (sum, sumsq) partials
  float4 bndU[2][2][512];  // clip upper bounds, SoA [rr][chunk][tid]
  float4 bndL[2][2][512];  // clip lower bounds
  float h[H];
  float te[H];
  float mod[R];
  float2 modred[16];       // per-warp (t0,t1) partials for s/m
  float2 red[16];          // prologue LN
  ull mbar[2];             // double-buffered tx barriers
};

__device__ __forceinline__ float sigm(float x) { return 1.0f / (1.0f + __expf(-x)); }

__device__ __forceinline__ void cluster_sync_() {
  asm volatile("barrier.cluster.arrive.aligned;\n\tbarrier.cluster.wait.aligned;" ::: "memory");
}

__device__ __forceinline__ uint32_t smem_u32(const void* p) {
  return (uint32_t)__cvta_generic_to_shared(p);
}

__device__ __forceinline__ uint32_t mapa_u32(uint32_t addr, uint32_t peer) {
  uint32_t r;
  asm("mapa.shared::cluster.u32 %0, %1, %2;" : "=r"(r) : "r"(addr), "r"(peer));
  return r;
}

__device__ __forceinline__ void st_async_2f(uint32_t raddr, float a, float b, uint32_t rmbar) {
  ull pk = (ull)__float_as_uint(a) | ((ull)__float_as_uint(b) << 32);
  asm volatile("st.async.shared::cluster.mbarrier::complete_tx::bytes.b64 [%0], %1, [%2];"
               :: "r"(raddr), "l"(pk), "r"(rmbar) : "memory");
}

__device__ __forceinline__ void mbar_arm(uint32_t mbar, uint32_t bytes) {
  asm volatile("mbarrier.arrive.expect_tx.shared.b64 _, [%0], %1;"
               :: "r"(mbar), "r"(bytes) : "memory");
}

__device__ __forceinline__ void mbar_init(uint32_t mbar, uint32_t count) {
  asm volatile("mbarrier.init.shared.b64 [%0], %1;" :: "r"(mbar), "r"(count) : "memory");
}

__device__ __forceinline__ void mbar_wait(uint32_t mbar, uint32_t parity) {
  uint32_t done;
  asm volatile("{\n\t.reg .pred p;\n\t"
               "mbarrier.try_wait.parity.acquire.cta.shared::cta.b64 p, [%1], %2;\n\t"
               "selp.b32 %0, 1, 0, p;\n\t}"
               : "=r"(done) : "r"(mbar), "r"(parity) : "memory");
  while (!done) {
    asm volatile("{\n\t.reg .pred p;\n\t"
                 "mbarrier.try_wait.parity.acquire.cta.shared::cta.b64 p, [%1], %2, 0x989680;\n\t"
                 "selp.b32 %0, 1, 0, p;\n\t}"
                 : "=r"(done) : "r"(mbar), "r"(parity) : "memory");
  }
}

// ---------- Blackwell f32x2 packed helpers ----------
__device__ __forceinline__ ull pack2(float lo, float hi) {
  ull r; asm("mov.b64 %0, {%1, %2};" : "=l"(r) : "f"(lo), "f"(hi)); return r;
}
__device__ __forceinline__ void unpack2(ull v, float& lo, float& hi) {
  asm("mov.b64 {%0, %1}, %2;" : "=f"(lo), "=f"(hi) : "l"(v));
}
__device__ __forceinline__ ull mul2(ull a, ull b) {
  ull d; asm("mul.rn.f32x2 %0, %1, %2;" : "=l"(d) : "l"(a), "l"(b)); return d;
}
__device__ __forceinline__ ull fma2(ull a, ull b, ull c) {
  ull d; asm("fma.rn.f32x2 %0, %1, %2, %3;" : "=l"(d) : "l"(a), "l"(b), "l"(c)); return d;
}

// packed dot: weight row in smem (2x LDS.128) with h2[4]
__device__ __forceinline__ float dotrow(const ulonglong2* Wrow, int lane, const ull* h2) {
  ulonglong2 wa = Wrow[lane];
  ulonglong2 wb = Wrow[32 + lane];
  ull acc = mul2(wa.x, h2[0]);
  acc = fma2(wa.y, h2[1], acc);
  acc = fma2(wb.x, h2[2], acc);
  acc = fma2(wb.y, h2[3], acc);
  float lo, hi; unpack2(acc, lo, hi);
  return lo + hi;
}

__global__ void __cluster_dims__(8, 1, 1) __launch_bounds__(512, 1)
sgru_persistent(const float* __restrict__ x_in,
                const float* __restrict__ h0,
                const float* __restrict__ v0,
                const float* __restrict__ dU0,
                const float* __restrict__ te0,
                const float* __restrict__ tE0,
                const float* __restrict__ Wx2h,
                const float* __restrict__ bx2h,
                const float* __restrict__ Wh2h,
                const float* __restrict__ bh2h,
                const float* __restrict__ lnxg,
                const float* __restrict__ lnxb,
                const float* __restrict__ lnhg,
                const float* __restrict__ lnhb,
                const float* __restrict__ Wh2mod,
                const float* __restrict__ bh2mod,
                const float* __restrict__ Wmod2h,
                const float* __restrict__ bmod2h,
                const float* __restrict__ alpha,
                const float* __restrict__ tauU,
                float* __restrict__ out)
{
  extern __shared__ unsigned char smem_raw[];
  SM* S = reinterpret_cast<SM*>(smem_raw);
  const int tid  = threadIdx.x;
  const int wid  = tid >> 5;
  const int lane = tid & 31;
  const int rank = blockIdx.x & 7;
  const int b    = blockIdx.x >> 3;
  const int gi0  = 32 * rank + 2 * wid;
  const bool lower = (tid < 256);
  const int  elem  = tid & 255;         // element this thread serves in phase 2

  const float a0      = alpha[0];
  const float sp_a    = (a0 > 0.f) ? (a0 + log1pf(expf(-a0))) : log1pf(expf(a0));
  const float inv_spa = 1.0f / sp_a;
  const float tau     = sigm(tauU[0]);
  const float bm0     = bmod2h[0];
  const float bm1     = bmod2h[1];
  const ull   omt2    = pack2(1.f - tau, 1.f - tau);

  // ================= prologue: Wx = x @ Wx2h^T + b (raw) =====================
  {
    const float4* WxA = (const float4*)(Wx2h + (size_t)96 * rank * I);
    float4* Ws4w = (float4*)S->Ws;
    for (int i = tid; i < 96 * I / 4; i += 512) Ws4w[i] = WxA[i];
  }
  __syncthreads();
  {
    const float4* Ws4c = (const float4*)S->Ws;
    for (int it = 0; it < 3; ++it) {
      int t = wid + 16 * it;
      float4 x4 = ((const float4*)x_in)[(size_t)(t * B + b) * 32 + lane];
      for (int g = 0; g < 6; ++g) {
        float acc[16];
#pragma unroll
        for (int k = 0; k < 16; ++k) {
          float4 w = Ws4c[(g * 16 + k) * 32 + lane];
          acc[k] = w.x * x4.x + w.y * x4.y + w.z * x4.z + w.w * x4.w;
        }
#pragma unroll
        for (int k = 0; k < 8; ++k) {
          float a = (lane & 16) ? acc[k + 8] : acc[k];
          float c = (lane & 16) ? acc[k] : acc[k + 8];
          acc[k] = a + __shfl_xor_sync(~0u, c, 16);
        }
#pragma unroll
        for (int k = 0; k < 4; ++k) {
          float a = (lane & 8) ? acc[k + 4] : acc[k];
          float c = (lane & 8) ? acc[k] : acc[k + 4];
          acc[k] = a + __shfl_xor_sync(~0u, c, 8);
        }
#pragma unroll
        for (int k = 0; k < 2; ++k) {
          float a = (lane & 4) ? acc[k + 2] : acc[k];
          float c = (lane & 4) ? acc[k] : acc[k + 2];
          acc[k] = a + __shfl_xor_sync(~0u, c, 4);
        }
#pragma unroll
        for (int o = 2; o; o >>= 1) {
          acc[0] += __shfl_xor_sync(~0u, acc[0], o);
          acc[1] += __shfl_xor_sync(~0u, acc[1], o);
        }
        if ((lane & 3) == 0) {
          int p = (lane >> 2) & 7;
          int o = 96 * rank + g * 16 + 2 * p;
          float2 bias = *(const float2*)&bx2h[o];
          float2 val = make_float2(acc[0] + bias.x, acc[1] + bias.y);
          *(float2*)&g_Wx[(size_t)(t * B + b) * H3 + o] = val;
        }
      }
    }
  }
  cluster_sync_();

  // ================= prologue LN over g_Wx ===================================
  for (int t = rank; t < T; t += 8) {
    float* base = &g_Wx[(size_t)(t * B + b) * H3];
    float e0 = base[tid];
    float e1 = (tid < 256) ? base[512 + tid] : 0.f;
    float s1 = e0 + e1, s2 = e0 * e0 + e1 * e1;
#pragma unroll
    for (int o = 16; o; o >>= 1) {
      s1 += __shfl_xor_sync(~0u, s1, o);
      s2 += __shfl_xor_sync(~0u, s2, o);
    }
    if (lane == 0) S->red[wid] = make_float2(s1, s2);
    __syncthreads();
    float ssum = 0.f, ssq = 0.f;
#pragma unroll
    for (int i = 0; i < 16; ++i) { float2 rr = S->red[i]; ssum += rr.x; ssq += rr.y; }
    float mu   = ssum * (1.0f / H3);
    float var  = ssq * (1.0f / H3) - mu * mu;
    float rstd = rsqrtf(var + 1e-5f);
    base[tid] = (e0 - mu) * rstd * lnxg[tid] + lnxb[tid];
    if (tid < 256)
      base[512 + tid] = (e1 - mu) * rstd * lnxg[512 + tid] + lnxb[512 + tid];
    __syncthreads();
  }

  // ================= load main-loop smem + register state ===================
  {
    float4* Ws4w = (float4*)S->Ws;
    for (int i = tid; i < 96 * 64; i += 512) {
      int q = i >> 6, c4 = i & 63;
      int grow = ((q >> 5) << 8) + 32 * rank + (q & 31);
      Ws4w[i] = ((const float4*)(Wh2h + (size_t)grow * H))[c4];
    }
    const float4* Wm4s = (const float4*)Wh2mod;
    float4* Wm4w = (float4*)S->Wm;
    for (int i = tid; i < 32 * 64; i += 512) Wm4w[i] = Wm4s[i];
  }
  // phase-2 split state: lower holds v; upper holds te + h replica
  float v_own = 0.f, te_rep = 0.f, h_rep = 0.f;
  float gA = lnhg[tid], lbA = lnhb[tid];           // lower: gamma0 ; upper: gamma1
  float gC = 0.f, lbC = 0.f;                       // lower only: gamma2
  if (lower) {
    v_own = v0[b * H + elem];
    S->h[elem] = h0[b * H + elem];
    gC = lnhg[512 + elem]; lbC = lnhb[512 + elem];
  } else {
    h_rep  = h0[b * H + elem];
    te_rep = te0[b * H + elem];
    S->te[elem] = te_rep;
  }

  const uint32_t mb_local = smem_u32(&S->mbar[0]);
  if (tid == 0) {
    mbar_init(mb_local, 1);
    mbar_init(mb_local + 8, 1);
    mbar_arm(mb_local, EXPECT_BYTES);
    mbar_arm(mb_local + 8, EXPECT_BYTES);
  }

  // per-lane fold pair p and preloaded bias pair
  const int pgrp = (lane >> 3) & 3;
  float pb0 = 0.f, pb1 = 0.f;
  if (pgrp < 3) {
    pb0 = bh2h[256 * pgrp + gi0];
    pb1 = bh2h[256 * pgrp + gi0 + 1];
  }
  const float wsA = Wmod2h[2 * wid], wsB = Wmod2h[2 * wid + 1];
  const float wmA = Wmod2h[R + 2 * wid], wmB = Wmod2h[R + 2 * wid + 1];
  const int   mrow = 2 * wid + ((lane >> 4) & 1);
  const float bhm_l = bh2mod[mrow];

  // dU / tE rows gi0, gi0+1 as PACKED f32x2 state; clip bounds -> smem SoA
  ull dU2[2][4], tE2[2][4];
#pragma unroll
  for (int rr = 0; rr < 2; ++rr) {
    int gi = gi0 + rr;
    const ulonglong2* du8 = (const ulonglong2*)(dU0 + ((size_t)b * H + gi) * H);
    const ulonglong2* tE8 = (const ulonglong2*)(tE0 + ((size_t)b * H + gi) * H);
    const float4* wv4 = (const float4*)(Wh2h + (size_t)(512 + gi) * H);
    ulonglong2 A = du8[lane], C = du8[32 + lane];
    dU2[rr][0] = A.x; dU2[rr][1] = A.y; dU2[rr][2] = C.x; dU2[rr][3] = C.y;
    A = tE8[lane]; C = tE8[32 + lane];
    tE2[rr][0] = A.x; tE2[rr][1] = A.y; tE2[rr][2] = C.x; tE2[rr][3] = C.y;
    float4 a = wv4[lane], c = wv4[32 + lane];
    float wv[8] = {a.x,a.y,a.z,a.w,c.x,c.y,c.z,c.w};
    float4 u0, u1, l0, l1;
    u0.x =  fmaxf(1.f - wv[0], 0.f) * inv_spa;
    u0.y =  fmaxf(1.f - wv[1], 0.f) * inv_spa;
    u0.z =  fmaxf(1.f - wv[2], 0.f) * inv_spa;
    u0.w =  fmaxf(1.f - wv[3], 0.f) * inv_spa;
    u1.x =  fmaxf(1.f - wv[4], 0.f) * inv_spa;
    u1.y =  fmaxf(1.f - wv[5], 0.f) * inv_spa;
    u1.z =  fmaxf(1.f - wv[6], 0.f) * inv_spa;
    u1.w =  fmaxf(1.f - wv[7], 0.f) * inv_spa;
    l0.x = -fmaxf(1.f + wv[0], 0.f) * inv_spa;
    l0.y = -fmaxf(1.f + wv[1], 0.f) * inv_spa;
    l0.z = -fmaxf(1.f + wv[2], 0.f) * inv_spa;
    l0.w = -fmaxf(1.f + wv[3], 0.f) * inv_spa;
    l1.x = -fmaxf(1.f + wv[4], 0.f) * inv_spa;
    l1.y = -fmaxf(1.f + wv[5], 0.f) * inv_spa;
    l1.z = -fmaxf(1.f + wv[6], 0.f) * inv_spa;
    l1.w = -fmaxf(1.f + wv[7], 0.f) * inv_spa;
    S->bndU[rr][0][tid] = u0; S->bndU[rr][1][tid] = u1;
    S->bndL[rr][0][tid] = l0; S->bndL[rr][1][tid] = l1;
  }

  const uint32_t whx_peer   = mapa_u32(smem_u32(&S->whx[0][0]),   lane & 7);
  const uint32_t stats_peer = mapa_u32(smem_u32(&S->stats[0][0]), lane & 7);
  const uint32_t mbar_peer  = mapa_u32(mb_local,                  lane & 7);

  cluster_sync_();   // orders mbarrier init + smem state cluster-wide

  // packed h column registers
  ull h2[4];
  {
    const ulonglong2* h8 = (const ulonglong2*)S->h;
    ulonglong2 a = h8[lane], c = h8[32 + lane];
    h2[0] = a.x; h2[1] = a.y; h2[2] = c.x; h2[3] = c.y;
  }

  // initial plastic partials (packed)
  float pp0, pp1;
  {
    ull p0 = mul2(dU2[0][0], h2[0]);
    p0 = fma2(dU2[0][1], h2[1], p0);
    p0 = fma2(dU2[0][2], h2[2], p0);
    p0 = fma2(dU2[0][3], h2[3], p0);
    ull p1 = mul2(dU2[1][0], h2[0]);
    p1 = fma2(dU2[1][1], h2[1], p1);
    p1 = fma2(dU2[1][2], h2[2], p1);
    p1 = fma2(dU2[1][3], h2[3], p1);
    float lo, hi;
    unpack2(p0, lo, hi); pp0 = lo + hi;
    unpack2(p1, lo, hi); pp1 = lo + hi;
  }

  const ulonglong2* Ws8 = (const ulonglong2*)S->Ws;
  const ulonglong2* Wm8 = (const ulonglong2*)S->Wm;

  // preloop: all 6 GEMV dots for t=0 (plastic added at loop top)
  float acc[6];
  acc[0] = dotrow(Ws8 + (2*wid)    * 64, lane, h2);
  acc[1] = dotrow(Ws8 + (2*wid+1)  * 64, lane, h2);
  acc[2] = dotrow(Ws8 + (32+2*wid) * 64, lane, h2);
  acc[3] = dotrow(Ws8 + (33+2*wid) * 64, lane, h2);
  acc[4] = dotrow(Ws8 + (64+2*wid) * 64, lane, h2);
  acc[5] = dotrow(Ws8 + (65+2*wid) * 64, lane, h2);

  // wx pipeline registers for t=0
  float wxA, wxC = 0.f;
  {
    const float* wxp = &g_Wx[(size_t)(0 * B + b) * H3];
    wxA = __ldcg(wxp + tid);                       // lower: wx0 ; upper: wx1
    if (lower) wxC = __ldcg(wxp + 512 + elem);     // lower: wx2
  }

  // ================= main scan ==============================================
  int par = 0;
  for (int t = 0; t < T; ++t, par ^= 1) {
    const uint32_t use_parity = (uint32_t)(t >> 1) & 1u;

    // ---- add plastic, fold 6 -> 2, stats, exchange ----
    acc[4] += sp_a * pp0;
    acc[5] += sp_a * pp1;
    // stage 1: fold (z0,z1,r0,r1) with (dv0,dv1,0,0) across lane bit 4
#pragma unroll
    for (int k = 0; k < 2; ++k) {
      float a = (lane & 16) ? acc[k + 4] : acc[k];
      float c = (lane & 16) ? acc[k] : acc[k + 4];
      acc[k] = a + __shfl_xor_sync(~0u, c, 16);
      // lanes>=16 that folded "0" slots just carry (z,r) halves
      float a2 = (lane & 16) ? 0.f : acc[k + 2];
      float c2 = (lane & 16) ? acc[k + 2] : 0.f;
      acc[k + 2] = a2 + __shfl_xor_sync(~0u, c2, 16);
    }
    // stage 2: fold across lane bit 3
#pragma unroll
    for (int k = 0; k < 2; ++k) {
      float a = (lane & 8) ? acc[k + 2] : acc[k];
      float c = (lane & 8) ? acc[k] : acc[k + 2];
      acc[k] = a + __shfl_xor_sync(~0u, c, 8);
    }
#pragma unroll
    for (int o = 4; o; o >>= 1) {
      acc[0] += __shfl_xor_sync(~0u, acc[0], o);
      acc[1] += __shfl_xor_sync(~0u, acc[1], o);
    }
    acc[0] += pb0; acc[1] += pb1;
    float u = acc[0] + acc[1];
    float q = acc[0] * acc[0] + acc[1] * acc[1];
    u += __shfl_xor_sync(~0u, u, 8);  q += __shfl_xor_sync(~0u, q, 8);
    u += __shfl_xor_sync(~0u, u, 16); q += __shfl_xor_sync(~0u, q, 16);

    {
      const uint32_t rmbar = mbar_peer + 8u * (uint32_t)par;
      if (pgrp < 3) {
        st_async_2f(whx_peer + (uint32_t)(par * H3 + 256 * pgrp + gi0) * 4u,
                    acc[0], acc[1], rmbar);
      } else {
        st_async_2f(stats_peer + (uint32_t)(par * 128 + rank * 16 + wid) * 8u,
                    u, q, rmbar);
      }
    }

    mbar_wait(mb_local + 8u * (uint32_t)par, use_parity);

    // ---- stats combine (all threads) + split phase 2 ----
    {
      const float4* st4 = (const float4*)&S->stats[par][0];
      float4 A = st4[lane], Bv = st4[32 + lane];
      float su = A.x + A.z + Bv.x + Bv.z;
      float sq = A.y + A.w + Bv.y + Bv.w;
#pragma unroll
      for (int o = 16; o; o >>= 1) {
        su += __shfl_xor_sync(~0u, su, o);
        sq += __shfl_xor_sync(~0u, sq, o);
      }
      float mu   = su * (1.0f / H3);
      float var  = sq * (1.0f / H3) - mu * mu;
      float rstd = rsqrtf(var + 1e-5f);

      if (lower) {
        float w0 = S->whx[par][elem];
        float w2 = S->whx[par][512 + elem];
        float pre0 = (w0 - mu) * rstd * gA + lbA + wxA;
        float pre2 = (w2 - mu) * rstd * gC + lbC + wxC;
        float z  = sigm(pre0);
        float vn = v_own + z * (pre2 - v_own);
        float hn = fmaxf(vn, 0.f);
        v_own = vn;
        S->h[elem] = hn;
        if (rank == 0) out[OUTS_OFF + (size_t)(t * B + b) * H + elem] = hn;
      } else {
        float w1 = S->whx[par][256 + elem];
        float pre1 = (w1 - mu) * rstd * gA + lbA + wxA;
        float r  = sigm(pre1);
        float tn = te_rep + r * (h_rep - te_rep);   // OLD h replica
        te_rep = tn;
        S->te[elem] = tn;
      }
    }
    __syncthreads();                               // (B)

    // ---- re-arm buffer par for step t+2 (off the critical path now) ----
    if (tid == 0) mbar_arm(mb_local + 8u * (uint32_t)par, EXPECT_BYTES);

    // ---- prefetch wx for t+1 (slack: consumed next iteration) ----
    if (t < T - 1) {
      const float* wxn = &g_Wx[(size_t)((t + 1) * B + b) * H3];
      wxA = __ldcg(wxn + tid);
      if (lower) wxC = __ldcg(wxn + 512 + elem);
    }

    // ---- reload packed h columns + own-row scalars; upper updates h replica ----
    float h_r0, h_r1, te_r0, te_r1;
    {
      const ulonglong2* h8 = (const ulonglong2*)S->h;
      ulonglong2 a = h8[lane], c = h8[32 + lane];
      h2[0] = a.x; h2[1] = a.y; h2[2] = c.x; h2[3] = c.y;
      h_r0 = S->h[gi0]; h_r1 = S->h[gi0 + 1];
      te_r0 = S->te[gi0]; te_r1 = S->te[gi0 + 1];
      if (!lower) h_rep = S->h[elem];
    }

    // ---- GEMV dots for NEXT step ----
    acc[0] = dotrow(Ws8 + (2*wid)    * 64, lane, h2);
    acc[1] = dotrow(Ws8 + (2*wid+1)  * 64, lane, h2);
    acc[2] = dotrow(Ws8 + (32+2*wid) * 64, lane, h2);
    acc[3] = dotrow(Ws8 + (33+2*wid) * 64, lane, h2);
    acc[4] = dotrow(Ws8 + (64+2*wid) * 64, lane, h2);
    acc[5] = dotrow(Ws8 + (65+2*wid) * 64, lane, h2);

    // ---- mod = relu(h_new @ Wm^T + b), 2 rows/warp + scalar partials ----
    {
      float m0 = dotrow(Wm8 + (wid * 2)     * 64, lane, h2);
      float m1 = dotrow(Wm8 + (wid * 2 + 1) * 64, lane, h2);
      float a = (lane & 16) ? m1 : m0;
      float c = (lane & 16) ? m0 : m1;
      float vsum = a + __shfl_xor_sync(~0u, c, 16);
#pragma unroll
      for (int o = 8; o; o >>= 1) vsum += __shfl_xor_sync(~0u, vsum, o);
      float mval  = fmaxf(vsum + bhm_l, 0.f);
      float other = __shfl_xor_sync(~0u, mval, 16);
      if (lane == 0) {
        S->modred[wid] = make_float2(wsA * mval + wsB * other,
                                     wmA * mval + wmB * other);
      }
      if ((lane & 15) == 0) S->mod[mrow] = mval;
    }
    __syncthreads();                               // (C)

    // ---- s, m from modred ----
    float2 mr = S->modred[lane & 15];
    float t0 = mr.x, t1 = mr.y;
#pragma unroll
    for (int o = 8; o; o >>= 1) {
      t0 += __shfl_xor_sync(~0u, t0, o);
      t1 += __shfl_xor_sync(~0u, t1, o);
    }
    float s = sigm(t0 + bm0);
    float m = t1 + bm1;
    if (rank == 0 && tid < R)
      out[MODS_OFF + (size_t)(t * B + b) * R + tid] = S->mod[tid];

    // ---- G: packed dU / tE update + clip + plastic partials (te from smem) ----
    {
      const ull s2   = pack2(s, s);
      const ull oms2 = pack2(1.f - s, 1.f - s);
      const float tm = tau * m;
      const ull tm2  = pack2(tm, tm);
      ull te2p[4];
      {
        const ulonglong2* t8 = (const ulonglong2*)S->te;
        ulonglong2 a = t8[lane], c = t8[32 + lane];
        te2p[0] = a.x; te2p[1] = a.y; te2p[2] = c.x; te2p[3] = c.y;
      }
#pragma unroll
      for (int rr = 0; rr < 2; ++rr) {
        float hni  = (rr == 0) ? h_r0 : h_r1;
        float teni = (rr == 0) ? te_r0 : te_r1;
        const ull hni2 = pack2(hni, hni);
        const ull nte2 = pack2(-teni, -teni);
        float4 u0 = S->bndU[rr][0][tid], u1 = S->bndU[rr][1][tid];
        float4 l0 = S->bndL[rr][0][tid], l1 = S->bndL[rr][1][tid];
        float up[8] = {u0.x,u0.y,u0.z,u0.w,u1.x,u1.y,u1.z,u1.w};
        float lo[8] = {l0.x,l0.y,l0.z,l0.w,l1.x,l1.y,l1.z,l1.w};
        ull pp2 = 0;
        bool first = true;
#pragma unroll
        for (int p = 0; p < 4; ++p) {
          ull outer = fma2(nte2, h2[p], mul2(hni2, te2p[p]));
          ull E = fma2(s2, outer, mul2(oms2, tE2[rr][p]));
          tE2[rr][p] = E;
          ull dt = fma2(tm2, E, mul2(omt2, dU2[rr][p]));
          float d0, d1; unpack2(dt, d0, d1);
          d0 = fminf(fmaxf(d0, lo[2*p]),     up[2*p]);
          d1 = fminf(fmaxf(d1, lo[2*p + 1]), up[2*p + 1]);
          ull dp = pack2(d0, d1);
          dU2[rr][p] = dp;
          if (first) { pp2 = mul2(dp, h2[p]); first = false; }
          else       { pp2 = fma2(dp, h2[p], pp2); }
        }
        float plo, phi; unpack2(pp2, plo, phi);
        if (rr == 0) pp0 = plo + phi; else pp1 = plo + phi;
      }
    }
  }

  // ================= epilogue ===============================================
  if (rank == 0) {
    if (lower) {
      out[V_OFF + b * H + elem] = v_own;
      out[H_OFF + b * H + elem] = S->h[elem];
    } else {
      out[TE_OFF + b * H + elem] = te_rep;
    }
  }
#pragma unroll
  for (int rr = 0; rr < 2; ++rr) {
    int gi = gi0 + rr;
    size_t rb = ((size_t)b * H + gi) * H;
    ulonglong2 a, c;
    a.x = dU2[rr][0]; a.y = dU2[rr][1];
    c.x = dU2[rr][2]; c.y = dU2[rr][3];
    ((ulonglong2*)(out + DU_OFF + rb))[lane]      = a;
    ((ulonglong2*)(out + DU_OFF + rb))[32 + lane] = c;
    a.x = tE2[rr][0]; a.y = tE2[rr][1];
    c.x = tE2[rr][2]; c.y = tE2[rr][3];
    ((ulonglong2*)(out + TEE_OFF + rb))[lane]      = a;
    ((ulonglong2*)(out + TEE_OFF + rb))[32 + lane] = c;
  }
}

extern "C" void kernel_launch(void* const* d_in, const int* in_sizes, int n_in,
                              void* d_out, int out_size) {
  (void)in_sizes; (void)n_in; (void)out_size;
  const float* x_in   = (const float*)d_in[0];
  const float* h0     = (const float*)d_in[1];
  const float* v0     = (const float*)d_in[2];
  const float* dU0    = (const float*)d_in[3];
  const float* te0    = (const float*)d_in[4];
  const float* tE0    = (const float*)d_in[5];
  const float* Wx2h   = (const float*)d_in[6];
  const float* bx2h   = (const float*)d_in[7];
  const float* Wh2h   = (const float*)d_in[8];
  const float* bh2h   = (const float*)d_in[9];
  const float* lnxg   = (const float*)d_in[10];
  const float* lnxb   = (const float*)d_in[11];
  const float* lnhg   = (const float*)d_in[12];
  const float* lnhb   = (const float*)d_in[13];
  const float* Wh2mod = (const float*)d_in[14];
  const float* bh2mod = (const float*)d_in[15];
  const float* Wmod2h = (const float*)d_in[16];
  const float* bmod2h = (const float*)d_in[17];
  const float* alpha  = (const float*)d_in[18];
  const float* tauU   = (const float*)d_in[19];
  float* out = (float*)d_out;

  cudaFuncSetAttribute(sgru_persistent,
                       cudaFuncAttributeMaxDynamicSharedMemorySize,
                       (int)sizeof(SM));
  sgru_persistent<<<B * 8, 512, sizeof(SM)>>>(
      x_in, h0, v0, dU0, te0, tE0, Wx2h, bx2h, Wh2h, bh2h,
      lnxg, lnxb, lnhg, lnhb, Wh2mod, bh2mod, Wmod2h, bmod2h,
      alpha, tauU, out);
}

// round 14
// speedup vs baseline: 1.4257x; 1.0695x over previous
#include <cuda_runtime.h>
#include <math.h>
#include <stdint.h>

namespace {
constexpr int H  = 256;
constexpr int I  = 128;
constexpr int R  = 32;
constexpr int B  = 16;
constexpr int T  = 48;
constexpr int H3 = 768;

constexpr long V_OFF    = 0;
constexpr long H_OFF    = V_OFF  + (long)B * H;
constexpr long DU_OFF   = H_OFF  + (long)B * H;
constexpr long TE_OFF   = DU_OFF + (long)B * H * H;
constexpr long TEE_OFF  = TE_OFF + (long)B * H;
constexpr long OUTS_OFF = TEE_OFF + (long)B * H * H;
constexpr long MODS_OFF = OUTS_OFF + (long)T * B * H;

constexpr unsigned EXPECT_BYTES = 4096;  // 8 peers * 16 warps * 4 stores * 8B
}

typedef unsigned long long ull;

__device__ float g_Wx[(size_t)T * B * H3];   // LN(x @ Wx2h^T + b), prologue

struct SM {
  float Ws[96 * 256];      // W_h2h slice, reordered: [0:32)=z, [32:64)=r, [64:96)=dv rows
  float Wm[32 * 256];      // W_h2mod
  float  whx[2][H3];       // st.async-exchanged pre-LN vector (bias+plastic included)
  float2 stats[2][128];    // st.async-exchanged per-warp (sum, sumsq) partials
  float4 bndU[2][2][512];  // clip upper bounds, SoA [rr][chunk][tid]
  float4 bndL[2][2][512];  // clip lower bounds
  float h[H];
  float te[H];
  float mod[R];
  float2 modred[16];       // per-warp (t0,t1) partials for s/m
  float2 red[16];          // prologue LN
  ull mbar[2];             // double-buffered tx barriers
};

__device__ __forceinline__ float sigm(float x) { return 1.0f / (1.0f + __expf(-x)); }

__device__ __forceinline__ void cluster_sync_() {
  asm volatile("barrier.cluster.arrive.aligned;\n\tbarrier.cluster.wait.aligned;" ::: "memory");
}

__device__ __forceinline__ uint32_t smem_u32(const void* p) {
  return (uint32_t)__cvta_generic_to_shared(p);
}

__device__ __forceinline__ uint32_t mapa_u32(uint32_t addr, uint32_t peer) {
  uint32_t r;
  asm("mapa.shared::cluster.u32 %0, %1, %2;" : "=r"(r) : "r"(addr), "r"(peer));
  return r;
}

__device__ __forceinline__ void st_async_2f(uint32_t raddr, float a, float b, uint32_t rmbar) {
  ull pk = (ull)__float_as_uint(a) | ((ull)__float_as_uint(b) << 32);
  asm volatile("st.async.shared::cluster.mbarrier::complete_tx::bytes.b64 [%0], %1, [%2];"
               :: "r"(raddr), "l"(pk), "r"(rmbar) : "memory");
}

__device__ __forceinline__ void mbar_arm(uint32_t mbar, uint32_t bytes) {
  asm volatile("mbarrier.arrive.expect_tx.shared.b64 _, [%0], %1;"
               :: "r"(mbar), "r"(bytes) : "memory");
}

__device__ __forceinline__ void mbar_init(uint32_t mbar, uint32_t count) {
  asm volatile("mbarrier.init.shared.b64 [%0], %1;" :: "r"(mbar), "r"(count) : "memory");
}

__device__ __forceinline__ void mbar_wait(uint32_t mbar, uint32_t parity) {
  uint32_t done;
  asm volatile("{\n\t.reg .pred p;\n\t"
               "mbarrier.try_wait.parity.acquire.cta.shared::cta.b64 p, [%1], %2;\n\t"
               "selp.b32 %0, 1, 0, p;\n\t}"
               : "=r"(done) : "r"(mbar), "r"(parity) : "memory");
  while (!done) {
    asm volatile("{\n\t.reg .pred p;\n\t"
                 "mbarrier.try_wait.parity.acquire.cta.shared::cta.b64 p, [%1], %2, 0x989680;\n\t"
                 "selp.b32 %0, 1, 0, p;\n\t}"
                 : "=r"(done) : "r"(mbar), "r"(parity) : "memory");
  }
}

// ---------- Blackwell f32x2 packed helpers ----------
__device__ __forceinline__ ull pack2(float lo, float hi) {
  ull r; asm("mov.b64 %0, {%1, %2};" : "=l"(r) : "f"(lo), "f"(hi)); return r;
}
__device__ __forceinline__ void unpack2(ull v, float& lo, float& hi) {
  asm("mov.b64 {%0, %1}, %2;" : "=f"(lo), "=f"(hi) : "l"(v));
}
__device__ __forceinline__ ull mul2(ull a, ull b) {
  ull d; asm("mul.rn.f32x2 %0, %1, %2;" : "=l"(d) : "l"(a), "l"(b)); return d;
}
__device__ __forceinline__ ull fma2(ull a, ull b, ull c) {
  ull d; asm("fma.rn.f32x2 %0, %1, %2, %3;" : "=l"(d) : "l"(a), "l"(b), "l"(c)); return d;
}

// packed dot: weight row in smem (2x LDS.128) with h2[4]
__device__ __forceinline__ float dotrow(const ulonglong2* Wrow, int lane, const ull* h2) {
  ulonglong2 wa = Wrow[lane];
  ulonglong2 wb = Wrow[32 + lane];
  ull acc = mul2(wa.x, h2[0]);
  acc = fma2(wa.y, h2[1], acc);
  acc = fma2(wb.x, h2[2], acc);
  acc = fma2(wb.y, h2[3], acc);
  float lo, hi; unpack2(acc, lo, hi);
  return lo + hi;
}

__global__ void __cluster_dims__(8, 1, 1) __launch_bounds__(512, 1)
sgru_persistent(const float* __restrict__ x_in,
                const float* __restrict__ h0,
                const float* __restrict__ v0,
                const float* __restrict__ dU0,
                const float* __restrict__ te0,
                const float* __restrict__ tE0,
                const float* __restrict__ Wx2h,
                const float* __restrict__ bx2h,
                const float* __restrict__ Wh2h,
                const float* __restrict__ bh2h,
                const float* __restrict__ lnxg,
                const float* __restrict__ lnxb,
                const float* __restrict__ lnhg,
                const float* __restrict__ lnhb,
                const float* __restrict__ Wh2mod,
                const float* __restrict__ bh2mod,
                const float* __restrict__ Wmod2h,
                const float* __restrict__ bmod2h,
                const float* __restrict__ alpha,
                const float* __restrict__ tauU,
                float* __restrict__ out)
{
  extern __shared__ unsigned char smem_raw[];
  SM* S = reinterpret_cast<SM*>(smem_raw);
  const int tid  = threadIdx.x;
  const int wid  = tid >> 5;
  const int lane = tid & 31;
  const int rank = blockIdx.x & 7;
  const int b    = blockIdx.x >> 3;
  const int gi0  = 32 * rank + 2 * wid;
  const bool lower = (tid < 256);
  const int  elem  = tid & 255;         // element this thread serves in phase 2

  const float a0      = alpha[0];
  const float sp_a    = (a0 > 0.f) ? (a0 + log1pf(expf(-a0))) : log1pf(expf(a0));
  const float inv_spa = 1.0f / sp_a;
  const float tau     = sigm(tauU[0]);
  const float bm0     = bmod2h[0];
  const float bm1     = bmod2h[1];
  const ull   omt2    = pack2(1.f - tau, 1.f - tau);

  // ================= prologue: Wx = x @ Wx2h^T + b (raw) =====================
  {
    const float4* WxA = (const float4*)(Wx2h + (size_t)96 * rank * I);
    float4* Ws4w = (float4*)S->Ws;
    for (int i = tid; i < 96 * I / 4; i += 512) Ws4w[i] = WxA[i];
  }
  __syncthreads();
  {
    const float4* Ws4c = (const float4*)S->Ws;
    for (int it = 0; it < 3; ++it) {
      int t = wid + 16 * it;
      float4 x4 = ((const float4*)x_in)[(size_t)(t * B + b) * 32 + lane];
      for (int g = 0; g < 6; ++g) {
        float acc[16];
#pragma unroll
        for (int k = 0; k < 16; ++k) {
          float4 w = Ws4c[(g * 16 + k) * 32 + lane];
          acc[k] = w.x * x4.x + w.y * x4.y + w.z * x4.z + w.w * x4.w;
        }
#pragma unroll
        for (int k = 0; k < 8; ++k) {
          float a = (lane & 16) ? acc[k + 8] : acc[k];
          float c = (lane & 16) ? acc[k] : acc[k + 8];
          acc[k] = a + __shfl_xor_sync(~0u, c, 16);
        }
#pragma unroll
        for (int k = 0; k < 4; ++k) {
          float a = (lane & 8) ? acc[k + 4] : acc[k];
          float c = (lane & 8) ? acc[k] : acc[k + 4];
          acc[k] = a + __shfl_xor_sync(~0u, c, 8);
        }
#pragma unroll
        for (int k = 0; k < 2; ++k) {
          float a = (lane & 4) ? acc[k + 2] : acc[k];
          float c = (lane & 4) ? acc[k] : acc[k + 2];
          acc[k] = a + __shfl_xor_sync(~0u, c, 4);
        }
#pragma unroll
        for (int o = 2; o; o >>= 1) {
          acc[0] += __shfl_xor_sync(~0u, acc[0], o);
          acc[1] += __shfl_xor_sync(~0u, acc[1], o);
        }
        if ((lane & 3) == 0) {
          int p = (lane >> 2) & 7;
          int o = 96 * rank + g * 16 + 2 * p;
          float2 bias = *(const float2*)&bx2h[o];
          float2 val = make_float2(acc[0] + bias.x, acc[1] + bias.y);
          *(float2*)&g_Wx[(size_t)(t * B + b) * H3 + o] = val;
        }
      }
    }
  }
  cluster_sync_();

  // ================= prologue LN over g_Wx ===================================
  for (int t = rank; t < T; t += 8) {
    float* base = &g_Wx[(size_t)(t * B + b) * H3];
    float e0 = base[tid];
    float e1 = (tid < 256) ? base[512 + tid] : 0.f;
    float s1 = e0 + e1, s2 = e0 * e0 + e1 * e1;
#pragma unroll
    for (int o = 16; o; o >>= 1) {
      s1 += __shfl_xor_sync(~0u, s1, o);
      s2 += __shfl_xor_sync(~0u, s2, o);
    }
    if (lane == 0) S->red[wid] = make_float2(s1, s2);
    __syncthreads();
    float ssum = 0.f, ssq = 0.f;
#pragma unroll
    for (int i = 0; i < 16; ++i) { float2 rr = S->red[i]; ssum += rr.x; ssq += rr.y; }
    float mu   = ssum * (1.0f / H3);
    float var  = ssq * (1.0f / H3) - mu * mu;
    float rstd = rsqrtf(var + 1e-5f);
    base[tid] = (e0 - mu) * rstd * lnxg[tid] + lnxb[tid];
    if (tid < 256)
      base[512 + tid] = (e1 - mu) * rstd * lnxg[512 + tid] + lnxb[512 + tid];
    __syncthreads();
  }

  // ================= load main-loop smem + register state ===================
  {
    float4* Ws4w = (float4*)S->Ws;
    for (int i = tid; i < 96 * 64; i += 512) {
      int q = i >> 6, c4 = i & 63;
      int grow = ((q >> 5) << 8) + 32 * rank + (q & 31);
      Ws4w[i] = ((const float4*)(Wh2h + (size_t)grow * H))[c4];
    }
    const float4* Wm4s = (const float4*)Wh2mod;
    float4* Wm4w = (float4*)S->Wm;
    for (int i = tid; i < 32 * 64; i += 512) Wm4w[i] = Wm4s[i];
  }
  // phase-2 split state: lower holds v; upper holds te + h replica
  float v_own = 0.f, te_rep = 0.f, h_rep = 0.f;
  float gA = lnhg[tid], lbA = lnhb[tid];           // lower: gamma0 ; upper: gamma1
  float gC = 0.f, lbC = 0.f;                       // lower only: gamma2
  if (lower) {
    v_own = v0[b * H + elem];
    S->h[elem] = h0[b * H + elem];
    gC = lnhg[512 + elem]; lbC = lnhb[512 + elem];
  } else {
    h_rep  = h0[b * H + elem];
    te_rep = te0[b * H + elem];
    S->te[elem] = te_rep;
  }

  const uint32_t mb_local = smem_u32(&S->mbar[0]);
  if (tid == 0) {
    mbar_init(mb_local, 1);
    mbar_init(mb_local + 8, 1);
    mbar_arm(mb_local, EXPECT_BYTES);
    mbar_arm(mb_local + 8, EXPECT_BYTES);
  }

  // per-lane fold pair p and preloaded bias pair
  const int pgrp = (lane >> 3) & 3;
  float pb0 = 0.f, pb1 = 0.f;
  if (pgrp < 3) {
    pb0 = bh2h[256 * pgrp + gi0];
    pb1 = bh2h[256 * pgrp + gi0 + 1];
  }
  const float wsA = Wmod2h[2 * wid], wsB = Wmod2h[2 * wid + 1];
  const float wmA = Wmod2h[R + 2 * wid], wmB = Wmod2h[R + 2 * wid + 1];
  const int   mrow = 2 * wid + ((lane >> 4) & 1);
  const float bhm_l = bh2mod[mrow];

  // dU / tE rows gi0, gi0+1 as PACKED f32x2 state; clip bounds -> smem SoA
  ull dU2[2][4], tE2[2][4];
#pragma unroll
  for (int rr = 0; rr < 2; ++rr) {
    int gi = gi0 + rr;
    const ulonglong2* du8 = (const ulonglong2*)(dU0 + ((size_t)b * H + gi) * H);
    const ulonglong2* tE8 = (const ulonglong2*)(tE0 + ((size_t)b * H + gi) * H);
    const float4* wv4 = (const float4*)(Wh2h + (size_t)(512 + gi) * H);
    ulonglong2 A = du8[lane], C = du8[32 + lane];
    dU2[rr][0] = A.x; dU2[rr][1] = A.y; dU2[rr][2] = C.x; dU2[rr][3] = C.y;
    A = tE8[lane]; C = tE8[32 + lane];
    tE2[rr][0] = A.x; tE2[rr][1] = A.y; tE2[rr][2] = C.x; tE2[rr][3] = C.y;
    float4 a = wv4[lane], c = wv4[32 + lane];
    float wv[8] = {a.x,a.y,a.z,a.w,c.x,c.y,c.z,c.w};
    float4 u0, u1, l0, l1;
    u0.x =  fmaxf(1.f - wv[0], 0.f) * inv_spa;
    u0.y =  fmaxf(1.f - wv[1], 0.f) * inv_spa;
    u0.z =  fmaxf(1.f - wv[2], 0.f) * inv_spa;
    u0.w =  fmaxf(1.f - wv[3], 0.f) * inv_spa;
    u1.x =  fmaxf(1.f - wv[4], 0.f) * inv_spa;
    u1.y =  fmaxf(1.f - wv[5], 0.f) * inv_spa;
    u1.z =  fmaxf(1.f - wv[6], 0.f) * inv_spa;
    u1.w =  fmaxf(1.f - wv[7], 0.f) * inv_spa;
    l0.x = -fmaxf(1.f + wv[0], 0.f) * inv_spa;
    l0.y = -fmaxf(1.f + wv[1], 0.f) * inv_spa;
    l0.z = -fmaxf(1.f + wv[2], 0.f) * inv_spa;
    l0.w = -fmaxf(1.f + wv[3], 0.f) * inv_spa;
    l1.x = -fmaxf(1.f + wv[4], 0.f) * inv_spa;
    l1.y = -fmaxf(1.f + wv[5], 0.f) * inv_spa;
    l1.z = -fmaxf(1.f + wv[6], 0.f) * inv_spa;
    l1.w = -fmaxf(1.f + wv[7], 0.f) * inv_spa;
    S->bndU[rr][0][tid] = u0; S->bndU[rr][1][tid] = u1;
    S->bndL[rr][0][tid] = l0; S->bndL[rr][1][tid] = l1;
  }

  const uint32_t whx_peer   = mapa_u32(smem_u32(&S->whx[0][0]),   lane & 7);
  const uint32_t stats_peer = mapa_u32(smem_u32(&S->stats[0][0]), lane & 7);
  const uint32_t mbar_peer  = mapa_u32(mb_local,                  lane & 7);

  cluster_sync_();   // orders mbarrier init + smem state cluster-wide

  // packed h column registers
  ull h2[4];
  {
    const ulonglong2* h8 = (const ulonglong2*)S->h;
    ulonglong2 a = h8[lane], c = h8[32 + lane];
    h2[0] = a.x; h2[1] = a.y; h2[2] = c.x; h2[3] = c.y;
  }

  // initial plastic partials (packed)
  float pp0, pp1;
  {
    ull p0 = mul2(dU2[0][0], h2[0]);
    p0 = fma2(dU2[0][1], h2[1], p0);
    p0 = fma2(dU2[0][2], h2[2], p0);
    p0 = fma2(dU2[0][3], h2[3], p0);
    ull p1 = mul2(dU2[1][0], h2[0]);
    p1 = fma2(dU2[1][1], h2[1], p1);
    p1 = fma2(dU2[1][2], h2[2], p1);
    p1 = fma2(dU2[1][3], h2[3], p1);
    float lo, hi;
    unpack2(p0, lo, hi); pp0 = lo + hi;
    unpack2(p1, lo, hi); pp1 = lo + hi;
  }

  const ulonglong2* Ws8 = (const ulonglong2*)S->Ws;
  const ulonglong2* Wm8 = (const ulonglong2*)S->Wm;

  // preloop: all 6 GEMV dots for t=0 (plastic added at loop top)
  float acc[8];
  acc[0] = dotrow(Ws8 + (2*wid)    * 64, lane, h2);
  acc[1] = dotrow(Ws8 + (2*wid+1)  * 64, lane, h2);
  acc[2] = dotrow(Ws8 + (32+2*wid) * 64, lane, h2);
  acc[3] = dotrow(Ws8 + (33+2*wid) * 64, lane, h2);
  acc[4] = dotrow(Ws8 + (64+2*wid) * 64, lane, h2);
  acc[5] = dotrow(Ws8 + (65+2*wid) * 64, lane, h2);

  // wx pipeline registers for t=0
  float wxA, wxC = 0.f;
  {
    const float* wxp = &g_Wx[(size_t)(0 * B + b) * H3];
    wxA = __ldcg(wxp + tid);                       // lower: wx0 ; upper: wx1
    if (lower) wxC = __ldcg(wxp + 512 + elem);     // lower: wx2
  }

  // ================= main scan (unroll 2: par constant-folded) ===============
#pragma unroll 2
  for (int t = 0; t < T; ++t) {
    const int par = t & 1;
    const uint32_t use_parity = (uint32_t)(t >> 1) & 1u;

    // ---- add plastic, fold 8 -> 2, stats, exchange ----
    acc[4] += sp_a * pp0;
    acc[5] += sp_a * pp1;
    acc[6] = 0.f; acc[7] = 0.f;
#pragma unroll
    for (int k = 0; k < 4; ++k) {
      float a = (lane & 16) ? acc[k + 4] : acc[k];
      float c = (lane & 16) ? acc[k] : acc[k + 4];
      acc[k] = a + __shfl_xor_sync(~0u, c, 16);
    }
#pragma unroll
    for (int k = 0; k < 2; ++k) {
      float a = (lane & 8) ? acc[k + 2] : acc[k];
      float c = (lane & 8) ? acc[k] : acc[k + 2];
      acc[k] = a + __shfl_xor_sync(~0u, c, 8);
    }
#pragma unroll
    for (int o = 4; o; o >>= 1) {
      acc[0] += __shfl_xor_sync(~0u, acc[0], o);
      acc[1] += __shfl_xor_sync(~0u, acc[1], o);
    }
    acc[0] += pb0; acc[1] += pb1;
    float u = acc[0] + acc[1];
    float q = acc[0] * acc[0] + acc[1] * acc[1];
    u += __shfl_xor_sync(~0u, u, 8);  q += __shfl_xor_sync(~0u, q, 8);
    u += __shfl_xor_sync(~0u, u, 16); q += __shfl_xor_sync(~0u, q, 16);

    {
      const uint32_t rmbar = mbar_peer + 8u * (uint32_t)par;
      if (pgrp < 3) {
        st_async_2f(whx_peer + (uint32_t)(par * H3 + 256 * pgrp + gi0) * 4u,
                    acc[0], acc[1], rmbar);
      } else {
        st_async_2f(stats_peer + (uint32_t)(par * 128 + rank * 16 + wid) * 8u,
                    u, q, rmbar);
      }
    }

    mbar_wait(mb_local + 8u * (uint32_t)par, use_parity);
    if (tid == 0) mbar_arm(mb_local + 8u * (uint32_t)par, EXPECT_BYTES);

    // ---- stats combine (all threads) + split phase 2 ----
    {
      const float4* st4 = (const float4*)&S->stats[par][0];
      float4 A = st4[lane], Bv = st4[32 + lane];
      float su = A.x + A.z + Bv.x + Bv.z;
      float sq = A.y + A.w + Bv.y + Bv.w;
#pragma unroll
      for (int o = 16; o; o >>= 1) {
        su += __shfl_xor_sync(~0u, su, o);
        sq += __shfl_xor_sync(~0u, sq, o);
      }
      float mu   = su * (1.0f / H3);
      float var  = sq * (1.0f / H3) - mu * mu;
      float rstd = rsqrtf(var + 1e-5f);

      if (lower) {
        float w0 = S->whx[par][elem];
        float w2 = S->whx[par][512 + elem];
        float pre0 = (w0 - mu) * rstd * gA + lbA + wxA;
        float pre2 = (w2 - mu) * rstd * gC + lbC + wxC;
        float z  = sigm(pre0);
        float vn = v_own + z * (pre2 - v_own);
        float hn = fmaxf(vn, 0.f);
        v_own = vn;
        S->h[elem] = hn;
        if (rank == 0) out[OUTS_OFF + (size_t)(t * B + b) * H + elem] = hn;
      } else {
        float w1 = S->whx[par][256 + elem];
        float pre1 = (w1 - mu) * rstd * gA + lbA + wxA;
        float r  = sigm(pre1);
        float tn = te_rep + r * (h_rep - te_rep);   // OLD h replica
        te_rep = tn;
        S->te[elem] = tn;
      }
    }
    __syncthreads();                               // (B)

    // ---- prefetch wx for t+1 (slack: consumed next iteration) ----
    if (t < T - 1) {
      const float* wxn = &g_Wx[(size_t)((t + 1) * B + b) * H3];
      wxA = __ldcg(wxn + tid);
      if (lower) wxC = __ldcg(wxn + 512 + elem);
    }

    // ---- reload packed h columns + own-row scalars; upper updates h replica ----
    float h_r0, h_r1, te_r0, te_r1;
    {
      const ulonglong2* h8 = (const ulonglong2*)S->h;
      ulonglong2 a = h8[lane], c = h8[32 + lane];
      h2[0] = a.x; h2[1] = a.y; h2[2] = c.x; h2[3] = c.y;
      h_r0 = S->h[gi0]; h_r1 = S->h[gi0 + 1];
      te_r0 = S->te[gi0]; te_r1 = S->te[gi0 + 1];
      if (!lower) h_rep = S->h[elem];
    }

    // ---- GEMV dots for NEXT step ----
    acc[0] = dotrow(Ws8 + (2*wid)    * 64, lane, h2);
    acc[1] = dotrow(Ws8 + (2*wid+1)  * 64, lane, h2);
    acc[2] = dotrow(Ws8 + (32+2*wid) * 64, lane, h2);
    acc[3] = dotrow(Ws8 + (33+2*wid) * 64, lane, h2);
    acc[4] = dotrow(Ws8 + (64+2*wid) * 64, lane, h2);
    acc[5] = dotrow(Ws8 + (65+2*wid) * 64, lane, h2);

    // ---- mod = relu(h_new @ Wm^T + b), 2 rows/warp + scalar partials ----
    {
      float m0 = dotrow(Wm8 + (wid * 2)     * 64, lane, h2);
      float m1 = dotrow(Wm8 + (wid * 2 + 1) * 64, lane, h2);
      float a = (lane & 16) ? m1 : m0;
      float c = (lane & 16) ? m0 : m1;
      float vsum = a + __shfl_xor_sync(~0u, c, 16);
#pragma unroll
      for (int o = 8; o; o >>= 1) vsum += __shfl_xor_sync(~0u, vsum, o);
      float mval  = fmaxf(vsum + bhm_l, 0.f);
      float other = __shfl_xor_sync(~0u, mval, 16);
      if (lane == 0) {
        S->modred[wid] = make_float2(wsA * mval + wsB * other,
                                     wmA * mval + wmB * other);
      }
      if ((lane & 15) == 0) S->mod[mrow] = mval;
    }
    __syncthreads();                               // (C)

    // ---- s, m from modred ----
    float2 mr = S->modred[lane & 15];
    float t0 = mr.x, t1 = mr.y;
#pragma unroll
    for (int o = 8; o; o >>= 1) {
      t0 += __shfl_xor_sync(~0u, t0, o);
      t1 += __shfl_xor_sync(~0u, t1, o);
    }
    float s = sigm(t0 + bm0);
    float m = t1 + bm1;
    if (rank == 0 && tid < R)
      out[MODS_OFF + (size_t)(t * B + b) * R + tid] = S->mod[tid];

    // ---- G: packed dU / tE update + clip + plastic partials (te from smem) ----
    {
      const ull s2   = pack2(s, s);
      const ull oms2 = pack2(1.f - s, 1.f - s);
      const float tm = tau * m;
      const ull tm2  = pack2(tm, tm);
      ull te2p[4];
      {
        const ulonglong2* t8 = (const ulonglong2*)S->te;
        ulonglong2 a = t8[lane], c = t8[32 + lane];
        te2p[0] = a.x; te2p[1] = a.y; te2p[2] = c.x; te2p[3] = c.y;
      }
#pragma unroll
      for (int rr = 0; rr < 2; ++rr) {
        float hni  = (rr == 0) ? h_r0 : h_r1;
        float teni = (rr == 0) ? te_r0 : te_r1;
        const ull hni2 = pack2(hni, hni);
        const ull nte2 = pack2(-teni, -teni);
        float4 u0 = S->bndU[rr][0][tid], u1 = S->bndU[rr][1][tid];
        float4 l0 = S->bndL[rr][0][tid], l1 = S->bndL[rr][1][tid];
        float up[8] = {u0.x,u0.y,u0.z,u0.w,u1.x,u1.y,u1.z,u1.w};
        float lo[8] = {l0.x,l0.y,l0.z,l0.w,l1.x,l1.y,l1.z,l1.w};
        ull pp2 = 0;
        bool first = true;
#pragma unroll
        for (int p = 0; p < 4; ++p) {
          ull outer = fma2(nte2, h2[p], mul2(hni2, te2p[p]));
          ull E = fma2(s2, outer, mul2(oms2, tE2[rr][p]));
          tE2[rr][p] = E;
          ull dt = fma2(tm2, E, mul2(omt2, dU2[rr][p]));
          float d0, d1; unpack2(dt, d0, d1);
          d0 = fminf(fmaxf(d0, lo[2*p]),     up[2*p]);
          d1 = fminf(fmaxf(d1, lo[2*p + 1]), up[2*p + 1]);
          ull dp = pack2(d0, d1);
          dU2[rr][p] = dp;
          if (first) { pp2 = mul2(dp, h2[p]); first = false; }
          else       { pp2 = fma2(dp, h2[p], pp2); }
        }
        float plo, phi; unpack2(pp2, plo, phi);
        if (rr == 0) pp0 = plo + phi; else pp1 = plo + phi;
      }
    }
  }

  // ================= epilogue ===============================================
  if (rank == 0) {
    if (lower) {
      out[V_OFF + b * H + elem] = v_own;
      out[H_OFF + b * H + elem] = S->h[elem];
    } else {
      out[TE_OFF + b * H + elem] = te_rep;
    }
  }
#pragma unroll
  for (int rr = 0; rr < 2; ++rr) {
    int gi = gi0 + rr;
    size_t rb = ((size_t)b * H + gi) * H;
    ulonglong2 a, c;
    a.x = dU2[rr][0]; a.y = dU2[rr][1];
    c.x = dU2[rr][2]; c.y = dU2[rr][3];
    ((ulonglong2*)(out + DU_OFF + rb))[lane]      = a;
    ((ulonglong2*)(out + DU_OFF + rb))[32 + lane] = c;
    a.x = tE2[rr][0]; a.y = tE2[rr][1];
    c.x = tE2[rr][2]; c.y = tE2[rr][3];
    ((ulonglong2*)(out + TEE_OFF + rb))[lane]      = a;
    ((ulonglong2*)(out + TEE_OFF + rb))[32 + lane] = c;
  }
}

extern "C" void kernel_launch(void* const* d_in, const int* in_sizes, int n_in,
                              void* d_out, int out_size) {
  (void)in_sizes; (void)n_in; (void)out_size;
  const float* x_in   = (const float*)d_in[0];
  const float* h0     = (const float*)d_in[1];
  const float* v0     = (const float*)d_in[2];
  const float* dU0    = (const float*)d_in[3];
  const float* te0    = (const float*)d_in[4];
  const float* tE0    = (const float*)d_in[5];
  const float* Wx2h   = (const float*)d_in[6];
  const float* bx2h   = (const float*)d_in[7];
  const float* Wh2h   = (const float*)d_in[8];
  const float* bh2h   = (const float*)d_in[9];
  const float* lnxg   = (const float*)d_in[10];
  const float* lnxb   = (const float*)d_in[11];
  const float* lnhg   = (const float*)d_in[12];
  const float* lnhb   = (const float*)d_in[13];
  const float* Wh2mod = (const float*)d_in[14];
  const float* bh2mod = (const float*)d_in[15];
  const float* Wmod2h = (const float*)d_in[16];
  const float* bmod2h = (const float*)d_in[17];
  const float* alpha  = (const float*)d_in[18];
  const float* tauU   = (const float*)d_in[19];
  float* out = (float*)d_out;

  cudaFuncSetAttribute(sgru_persistent,
                       cudaFuncAttributeMaxDynamicSharedMemorySize,
                       (int)sizeof(SM));
  sgru_persistent<<<B * 8, 512, sizeof(SM)>>>(
      x_in, h0, v0, dU0, te0, tE0, Wx2h, bx2h, Wh2h, bh2h,
      lnxg, lnxb, lnhg, lnhb, Wh2mod, bh2mod, Wmod2h, bmod2h,
      alpha, tauU, out);
}